// round 15
// baseline (speedup 1.0000x reference)
#include <cuda_runtime.h>
#include <cuda_fp16.h>
#include <cstdint>
#include <cstddef>

#define B_ 8
#define C_ 512
#define S_ 1024
#define NH 8
#define HD 64
#define M_ (B_ * S_)   // 8192
#define NQKV 1536

// ---------------- scratch (device globals, no allocation) ----------------
__device__ __align__(16) float g_xs[M_ * C_];
__device__ __align__(16) float g_out1[M_ * C_];
__device__ __align__(16) __half g_res_h[M_ * C_];
__device__ __align__(16) __half g_res_l[M_ * C_];
__device__ __align__(16) __half g_qkv_h[M_ * NQKV];
__device__ __align__(16) __half g_qkv_l[M_ * NQKV];
__device__ __align__(16) __half g_o_h[M_ * C_];
__device__ __align__(16) __half g_o_l[M_ * C_];
__device__ __align__(16) __half g_h_h[M_ * C_];
__device__ __align__(16) __half g_h_l[M_ * C_];
__device__ __align__(16) __half g_h1_h[M_ * C_];
__device__ __align__(16) __half g_h1_l[M_ * C_];
__device__ __align__(16) __half g_wqkv_h[NQKV * C_];
__device__ __align__(16) __half g_wqkv_l[NQKV * C_];
__device__ __align__(16) __half g_wo_h[C_ * C_];
__device__ __align__(16) __half g_wo_l[C_ * C_];
__device__ __align__(16) __half g_w1_h[C_ * C_];
__device__ __align__(16) __half g_w1_l[C_ * C_];
__device__ __align__(16) __half g_w2_h[C_ * C_];
__device__ __align__(16) __half g_w2_l[C_ * C_];
__device__ float g_bqkv[NQKV];

// ---------------- PTX helpers (sm_80-level, valid on plain sm_103) ----------------
__device__ __forceinline__ uint32_t smem_to_u32(const void* p) {
    uint32_t a;
    asm("{ .reg .u64 t; cvta.to.shared.u64 t, %1; cvt.u32.u64 %0, t; }" : "=r"(a) : "l"(p));
    return a;
}
__device__ __forceinline__ uint32_t sw128(uint32_t off) { return off ^ ((off >> 3) & 0x70); }

__device__ __forceinline__ void mma_f16(float* c, const uint32_t* a, const uint32_t* b) {
    asm volatile(
        "mma.sync.aligned.m16n8k16.row.col.f32.f16.f16.f32 "
        "{%0,%1,%2,%3}, {%4,%5,%6,%7}, {%8,%9}, {%0,%1,%2,%3};"
        : "+f"(c[0]), "+f"(c[1]), "+f"(c[2]), "+f"(c[3])
        : "r"(a[0]), "r"(a[1]), "r"(a[2]), "r"(a[3]), "r"(b[0]), "r"(b[1]));
}
__device__ __forceinline__ void ldsm_x4(uint32_t* r, uint32_t addr) {
    asm volatile("ldmatrix.sync.aligned.m8n8.x4.shared.b16 {%0,%1,%2,%3}, [%4];"
        : "=r"(r[0]), "=r"(r[1]), "=r"(r[2]), "=r"(r[3]) : "r"(addr));
}
__device__ __forceinline__ void ldsm_x4_t(uint32_t* r, uint32_t addr) {
    asm volatile("ldmatrix.sync.aligned.m8n8.x4.trans.shared.b16 {%0,%1,%2,%3}, [%4];"
        : "=r"(r[0]), "=r"(r[1]), "=r"(r[2]), "=r"(r[3]) : "r"(addr));
}
#define CP_ASYNC16(dst, src) \
    asm volatile("cp.async.cg.shared.global [%0], [%1], 16;" :: "r"(dst), "l"(src))
#define CP_COMMIT() asm volatile("cp.async.commit_group;" ::: "memory")
#define CP_WAIT0() asm volatile("cp.async.wait_group 0;" ::: "memory")

// ---------------- small helpers ----------------
__device__ __forceinline__ float blockReduceSum(float v, float* red) {
    #pragma unroll
    for (int o = 16; o; o >>= 1) v += __shfl_xor_sync(0xffffffffu, v, o);
    int wid = threadIdx.x >> 5;
    if ((threadIdx.x & 31) == 0) red[wid] = v;
    __syncthreads();
    float r = (threadIdx.x < 8) ? red[threadIdx.x] : 0.f;
    if (threadIdx.x < 32) {
        #pragma unroll
        for (int o = 4; o; o >>= 1) r += __shfl_xor_sync(0xffffffffu, r, o);
        if (threadIdx.x == 0) red[0] = r;
    }
    __syncthreads();
    float out = red[0];
    __syncthreads();
    return out;
}
__device__ __forceinline__ void split_f16(float v, __half& h, __half& l) {
    h = __float2half_rn(v);
    l = __float2half_rn(v - __half2float(h));
}
__device__ __forceinline__ uint32_t pack_hi(float a, float b) {
    __half ha = __float2half_rn(a), hb = __float2half_rn(b);
    return ((uint32_t)__half_as_ushort(hb) << 16) | __half_as_ushort(ha);
}
__device__ __forceinline__ uint32_t pack_lo(float a, float b) {
    __half ha = __float2half_rn(a), hb = __float2half_rn(b);
    __half la = __float2half_rn(a - __half2float(ha));
    __half lb = __float2half_rn(b - __half2float(hb));
    return ((uint32_t)__half_as_ushort(lb) << 16) | __half_as_ushort(la);
}

// ---------------- pack kernels ----------------
__global__ void pack_qkvw(const float* __restrict__ QW, const float* __restrict__ KW,
                          const float* __restrict__ VW,
                          __half* __restrict__ wh, __half* __restrict__ wl) {
    __shared__ float t[32][33];
    int sel = blockIdx.z >> 3, n = blockIdx.z & 7;
    const float* src = sel == 0 ? QW : (sel == 1 ? KW : VW);
    float sc = sel == 0 ? 0.04419417382415922f : 1.f;
    int c0 = blockIdx.x * 32, d0 = blockIdx.y * 32;
    int lx = threadIdx.x & 31, ly = threadIdx.x >> 5;
    #pragma unroll
    for (int i = 0; i < 4; i++)
        t[ly + i * 8][lx] = src[((size_t)n * C_ + c0 + ly + i * 8) * HD + d0 + lx] * sc;
    __syncthreads();
    #pragma unroll
    for (int i = 0; i < 4; i++) {
        int row = sel * 512 + n * 64 + d0 + ly + i * 8;
        float v = t[lx][ly + i * 8];
        __half h, l; split_f16(v, h, l);
        wh[(size_t)row * C_ + c0 + lx] = h;
        wl[(size_t)row * C_ + c0 + lx] = l;
    }
}
__global__ void pack_w3(const float* __restrict__ OW, const float* __restrict__ W1,
                        const float* __restrict__ W2,
                        __half* __restrict__ oh, __half* __restrict__ ol,
                        __half* __restrict__ h1, __half* __restrict__ l1,
                        __half* __restrict__ h2, __half* __restrict__ l2) {
    __shared__ float t[32][33];
    const float* src = blockIdx.z == 0 ? OW : (blockIdx.z == 1 ? W1 : W2);
    __half* dh = blockIdx.z == 0 ? oh : (blockIdx.z == 1 ? h1 : h2);
    __half* dl = blockIdx.z == 0 ? ol : (blockIdx.z == 1 ? l1 : l2);
    int n0 = blockIdx.x * 32, k0 = blockIdx.y * 32;
    int lx = threadIdx.x & 31, ly = threadIdx.x >> 5;
    #pragma unroll
    for (int i = 0; i < 4; i++)
        t[ly + i * 8][lx] = src[(size_t)(k0 + ly + i * 8) * C_ + n0 + lx];
    __syncthreads();
    #pragma unroll
    for (int i = 0; i < 4; i++) {
        int n = n0 + ly + i * 8;
        float v = t[lx][ly + i * 8];
        __half h, l; split_f16(v, h, l);
        dh[(size_t)n * C_ + k0 + lx] = h;
        dl[(size_t)n * C_ + k0 + lx] = l;
    }
}
__global__ void pack_bias(const float* __restrict__ Qb, const float* __restrict__ Kb,
                          const float* __restrict__ Vb, float* __restrict__ b) {
    int j = blockIdx.x * blockDim.x + threadIdx.x;
    if (j < 512) b[j] = Qb[j] * 0.04419417382415922f;
    else if (j < 1024) b[j] = Kb[j - 512];
    else if (j < 1536) b[j] = Vb[j - 1024];
}

// ---------------- fused transpose + LayerNorm1 ----------------
static constexpr int LN1_SMEM = 512 * 36 * 4 + 256;
__global__ void __launch_bounds__(256)
ln1_fused(const float* __restrict__ x, const float* __restrict__ g,
          const float* __restrict__ bt, float* __restrict__ xs,
          __half* __restrict__ resh, __half* __restrict__ resl) {
    extern __shared__ float T[];   // [512][36] + stats[64]
    float* sred = T + 512 * 36;
    int tid = threadIdx.x;
    int bi = blockIdx.x >> 5;
    int s0 = (blockIdx.x & 31) * 32;
    #pragma unroll
    for (int it = 0; it < 64; it++) {
        int flat = tid + it * 256;
        int c = flat >> 5, s = flat & 31;
        T[c * 36 + s] = x[((size_t)bi * C_ + c) * S_ + s0 + s];
    }
    __syncthreads();
    int rt = tid >> 3, j = tid & 7;
    float sum = 0.f;
    #pragma unroll
    for (int i = 0; i < 64; i++) sum += T[(j + 8 * i) * 36 + rt];
    sum += __shfl_xor_sync(0xffffffffu, sum, 1);
    sum += __shfl_xor_sync(0xffffffffu, sum, 2);
    sum += __shfl_xor_sync(0xffffffffu, sum, 4);
    float mu = sum * (1.f / 512.f);
    float var = 0.f;
    #pragma unroll
    for (int i = 0; i < 64; i++) {
        float d = T[(j + 8 * i) * 36 + rt] - mu;
        var += d * d;
    }
    var += __shfl_xor_sync(0xffffffffu, var, 1);
    var += __shfl_xor_sync(0xffffffffu, var, 2);
    var += __shfl_xor_sync(0xffffffffu, var, 4);
    float rstd = rsqrtf(var * (1.f / 512.f) + 1e-5f);
    if (j == 0) { sred[rt * 2] = mu; sred[rt * 2 + 1] = rstd; }
    __syncthreads();
    #pragma unroll
    for (int it = 0; it < 32; it++) {
        int flat = tid + it * 256;
        int r = flat >> 8;
        int c2 = (flat & 255) * 2;
        float mur = sred[r * 2], rs = sred[r * 2 + 1];
        float v0 = T[c2 * 36 + r], v1 = T[(c2 + 1) * 36 + r];
        float y0 = (v0 - mur) * rs * g[c2] + bt[c2];
        float y1 = (v1 - mur) * rs * g[c2 + 1] + bt[c2 + 1];
        size_t row = (size_t)bi * S_ + s0 + r;
        *(float2*)(xs + row * C_ + c2) = make_float2(v0, v1);
        *(uint32_t*)(resh + row * C_ + c2) = pack_hi(y0, y1);
        *(uint32_t*)(resl + row * C_ + c2) = pack_lo(y0, y1);
    }
}

// ---------------- LayerNorm over rows -> fp16 hi/lo ----------------
__global__ void ln_rows_hl(const float* __restrict__ in, const float* __restrict__ g,
                           const float* __restrict__ bt,
                           __half* __restrict__ oh, __half* __restrict__ ol) {
    int row = blockIdx.x;
    int tid = threadIdx.x;
    __shared__ float red[8];
    const float* xp = in + (size_t)row * C_;
    float2 v = *(const float2*)(xp + tid * 2);
    float sum = blockReduceSum(v.x + v.y, red);
    float mu = sum * (1.f / 512.f);
    float d1 = v.x - mu, d2 = v.y - mu;
    float var = blockReduceSum(d1 * d1 + d2 * d2, red) * (1.f / 512.f);
    float rstd = rsqrtf(var + 1e-5f);
    float y1 = d1 * rstd * g[2 * tid] + bt[2 * tid];
    float y2 = d2 * rstd * g[2 * tid + 1] + bt[2 * tid + 1];
    *(uint32_t*)(oh + (size_t)row * C_ + 2 * tid) = pack_hi(y1, y2);
    *(uint32_t*)(ol + (size_t)row * C_ + 2 * tid) = pack_lo(y1, y2);
}

// ---------------- GEMM body: 128x256 tile, 512 threads, 2-stage cp.async ----------------
// TERMS: 3 = Ah*Bh+Ah*Bl+Al*Bh, 2 = Ah*Bh+Ah*Bl, 1 = Ah*Bh,
//        4 = Ah*Bh+Al*Bh (A hi/lo, B hi only)
// OUT: 0 = fp32 row-major, 1 = fp16 hi/lo, 2 = fp32 transposed BCHW via smem restage
// Stage layout: A 16KB @ +0, B 32KB @ +16K; stage stride 48KB; total 96KB
static constexpr int GEMM_SMEM = 98304;

template <int ACT, int RESID, int OUT, int TERMS>
__device__ __forceinline__ void gemm_body(
        char* smem,
        const __half* __restrict__ Ah, const __half* __restrict__ Al,
        const __half* __restrict__ Bh, const __half* __restrict__ Bl,
        const float* __restrict__ bias, const float* __restrict__ resid,
        float* __restrict__ outf, __half* __restrict__ outh,
        __half* __restrict__ outl, int ldo, int col0, int row0) {
    constexpr bool A_LO = (TERMS == 3 || TERMS == 4);
    constexpr bool B_LO = (TERMS == 3 || TERMS == 2);
    uint32_t sb = smem_to_u32(smem);
    int tid = threadIdx.x, wid = tid >> 5, lid = tid & 31;
    int grp = lid >> 2, qd = lid & 3;
    int m_base = (wid >> 2) * 32, n_base = (wid & 3) * 64;
    float acc[2][8][4] = {};

    auto issue = [&](int c) {
        int k0 = c * 32;
        uint32_t st = sb + (uint32_t)(c & 1) * 49152u;
        #pragma unroll
        for (int it = 0; it < (A_LO ? 2 : 1); it++) {
            int idx = tid + it * 512;
            int hl = idx >> 9, rem = idx & 511, r = rem >> 2, u = rem & 3;
            const __half* src = (hl ? Al : Ah) + (size_t)(row0 + r) * C_ + k0 + u * 8;
            CP_ASYNC16(st + sw128((uint32_t)(r * 128 + hl * 64 + u * 16)), src);
        }
        #pragma unroll
        for (int it = 0; it < (B_LO ? 4 : 2); it++) {
            int idx = tid + it * 512;
            int hl = idx >> 10, rem = idx & 1023, r = rem >> 2, u = rem & 3;
            const __half* src = (hl ? Bl : Bh) + (size_t)(col0 + r) * C_ + k0 + u * 8;
            CP_ASYNC16(st + 16384u + sw128((uint32_t)(r * 128 + hl * 64 + u * 16)), src);
        }
    };
    issue(0); CP_COMMIT();

    for (int c = 0; c < 16; c++) {
        CP_WAIT0();
        __syncthreads();
        if (c + 1 < 16) { issue(c + 1); CP_COMMIT(); }
        uint32_t Ab = sb + (uint32_t)(c & 1) * 49152u, Bb = Ab + 16384u;
        #pragma unroll
        for (int ks = 0; ks < 2; ks++) {
            uint32_t ah[2][4], al[2][4];
            #pragma unroll
            for (int f2 = 0; f2 < 2; f2++) {
                int r = m_base + f2 * 16 + (lid & 15);
                int u = ks * 2 + (lid >> 4);
                ldsm_x4(ah[f2], Ab + sw128((uint32_t)(r * 128 + u * 16)));
                if (A_LO)
                    ldsm_x4(al[f2], Ab + sw128((uint32_t)(r * 128 + 64 + u * 16)));
            }
            #pragma unroll
            for (int ntp = 0; ntp < 4; ntp++) {
                int rb = n_base + ntp * 16 + ((lid >> 4) << 3) + (lid & 7);
                int u = ks * 2 + ((lid >> 3) & 1);
                uint32_t bh[4], bl[4];
                ldsm_x4(bh, Bb + sw128((uint32_t)(rb * 128 + u * 16)));
                if (B_LO)
                    ldsm_x4(bl, Bb + sw128((uint32_t)(rb * 128 + 64 + u * 16)));
                #pragma unroll
                for (int f2 = 0; f2 < 2; f2++) {
                    mma_f16(acc[f2][ntp * 2], ah[f2], bh);
                    if (B_LO) mma_f16(acc[f2][ntp * 2], ah[f2], bl);
                    if (A_LO && TERMS != 2) mma_f16(acc[f2][ntp * 2], al[f2], bh);
                    mma_f16(acc[f2][ntp * 2 + 1], ah[f2], bh + 2);
                    if (B_LO) mma_f16(acc[f2][ntp * 2 + 1], ah[f2], bl + 2);
                    if (A_LO && TERMS != 2) mma_f16(acc[f2][ntp * 2 + 1], al[f2], bh + 2);
                }
            }
        }
        __syncthreads();
    }

    if (OUT == 2) {
        // transpose epilogue: 4 groups of 64 cols, stage fp32 [64][132], write BCHW
        float* T = (float*)smem;
        int b = row0 >> 10, s0 = row0 & 1023;
        #pragma unroll
        for (int quarter = 0; quarter < 4; quarter++) {
            __syncthreads();
            if ((wid & 3) == quarter) {
                #pragma unroll
                for (int f2 = 0; f2 < 2; f2++) {
                    #pragma unroll
                    for (int rr = 0; rr < 2; rr++) {
                        int rloc = m_base + f2 * 16 + grp + rr * 8;
                        #pragma unroll
                        for (int t = 0; t < 8; t++) {
                            int lc = t * 8 + qd * 2;
                            int col = col0 + quarter * 64 + lc;
                            float v0 = acc[f2][t][rr * 2 + 0] + bias[col];
                            float v1 = acc[f2][t][rr * 2 + 1] + bias[col + 1];
                            if (RESID) {
                                float2 rv = *(const float2*)(resid + (size_t)(row0 + rloc) * C_ + col);
                                v0 += rv.x; v1 += rv.y;
                            }
                            T[lc * 132 + rloc] = v0;
                            T[(lc + 1) * 132 + rloc] = v1;
                        }
                    }
                }
            }
            __syncthreads();
            #pragma unroll
            for (int it = 0; it < 16; it++) {
                int flat = tid + it * 512;
                int lc = flat >> 7, rr = flat & 127;
                outf[((size_t)b * C_ + col0 + quarter * 64 + lc) * S_ + s0 + rr] = T[lc * 132 + rr];
            }
        }
    } else {
        #pragma unroll
        for (int f2 = 0; f2 < 2; f2++) {
            #pragma unroll
            for (int rr = 0; rr < 2; rr++) {
                int r = row0 + m_base + f2 * 16 + grp + rr * 8;
                #pragma unroll
                for (int t = 0; t < 8; t++) {
                    int col = col0 + n_base + t * 8 + qd * 2;
                    float v0 = acc[f2][t][rr * 2 + 0] + bias[col];
                    float v1 = acc[f2][t][rr * 2 + 1] + bias[col + 1];
                    if (ACT == 1) {
                        v0 = 0.5f * v0 * (1.f + erff(v0 * 0.7071067811865476f));
                        v1 = 0.5f * v1 * (1.f + erff(v1 * 0.7071067811865476f));
                    }
                    if (RESID) {
                        float2 rv = *(const float2*)(resid + (size_t)r * C_ + col);
                        v0 += rv.x; v1 += rv.y;
                    }
                    if (OUT == 1) {
                        *(uint32_t*)(outh + (size_t)r * ldo + col) = pack_hi(v0, v1);
                        *(uint32_t*)(outl + (size_t)r * ldo + col) = pack_lo(v0, v1);
                    } else {
                        *(float2*)(outf + (size_t)r * ldo + col) = make_float2(v0, v1);
                    }
                }
            }
        }
    }
}

template <int ACT, int RESID, int OUT, int TERMS>
__global__ void __launch_bounds__(512, 1)
tc_gemm5(const __half* __restrict__ Ah, const __half* __restrict__ Al,
         const __half* __restrict__ Bh, const __half* __restrict__ Bl,
         const float* __restrict__ bias, const float* __restrict__ resid,
         float* __restrict__ outf, __half* __restrict__ outh,
         __half* __restrict__ outl, int ldo) {
    extern __shared__ char smem[];
    gemm_body<ACT, RESID, OUT, TERMS>(smem, Ah, Al, Bh, Bl, bias, resid,
                                      outf, outh, outl, ldo,
                                      blockIdx.x * 256, blockIdx.y * 128);
}

// fused QKV projection: col tiles 0..3 (q,k cols 0..1023) 3-term, 4..5 (v) TERMS=4
__global__ void __launch_bounds__(512, 1)
qkv_gemm(const __half* __restrict__ Ah, const __half* __restrict__ Al,
         const __half* __restrict__ Bh, const __half* __restrict__ Bl,
         const float* __restrict__ bias,
         __half* __restrict__ outh, __half* __restrict__ outl) {
    extern __shared__ char smem[];
    int col0 = blockIdx.x * 256, row0 = blockIdx.y * 128;
    if (blockIdx.x < 4)
        gemm_body<0, 0, 1, 3>(smem, Ah, Al, Bh, Bl, bias, nullptr,
                              nullptr, outh, outl, NQKV, col0, row0);
    else
        gemm_body<0, 0, 1, 4>(smem, Ah, Al, Bh, Bl, bias, nullptr,
                              nullptr, outh, outl, NQKV, col0, row0);
}

// ---------------- flash attention: QK 3-term, PV 1-term (V hi only) ----------------
// SMEM: QH 16K | QL 16K | 2 KV stages x 32K (KH|KL|VH used, 8K hole) = 96KB
static constexpr int ATT_SMEM = 98304;

__global__ void __launch_bounds__(256, 2)
attn4(const __half* __restrict__ qh, const __half* __restrict__ ql,
      __half* __restrict__ oh, __half* __restrict__ ol) {
    extern __shared__ char smem[];
    uint32_t sb = smem_to_u32(smem);
    const uint32_t QH = sb, QL = sb + 16384u;
    int tid = threadIdx.x, wid = tid >> 5, lid = tid & 31;
    int grp = lid >> 2, qd = lid & 3;
    int qt = blockIdx.x, n = blockIdx.y, b = blockIdx.z;
    size_t qrow0 = (size_t)(b * S_ + qt * 128);
    size_t obase = qrow0 * C_ + n * HD;
    int r0 = wid * 16;

    auto issue_kv = [&](int kt) {
        uint32_t st = sb + 32768u + (uint32_t)(kt & 1) * 32768u;
        #pragma unroll
        for (int it = 0; it < 6; it++) {
            int idx = tid + it * 256;
            int buf = idx >> 9, rem = idx & 511, r = rem >> 3, u = rem & 7;
            const __half* base = (buf == 1) ? ql : qh;
            int off = (buf == 2) ? 1024 : 512;
            const __half* src = base +
                (size_t)(b * S_ + kt * 64 + r) * NQKV + off + n * HD + u * 8;
            CP_ASYNC16(st + (uint32_t)(buf * 8192) +
                       sw128((uint32_t)(r * 128 + u * 16)), src);
        }
    };
    #pragma unroll
    for (int it = 0; it < 8; it++) {
        int idx = tid + it * 256;
        int hl = idx >> 10, rem = idx & 1023, r = rem >> 3, u = rem & 7;
        const __half* src = (hl ? ql : qh) + (qrow0 + r) * NQKV + n * HD + u * 8;
        CP_ASYNC16((hl ? QL : QH) + sw128((uint32_t)(r * 128 + u * 16)), src);
    }
    issue_kv(0); CP_COMMIT();

    float Oa[8][4] = {};
    float m0 = -1e30f, m1 = -1e30f, l0 = 0.f, l1 = 0.f;

    for (int kt = 0; kt < 16; kt++) {
        CP_WAIT0();
        __syncthreads();
        if (kt + 1 < 16) { issue_kv(kt + 1); CP_COMMIT(); }
        uint32_t KHs = sb + 32768u + (uint32_t)(kt & 1) * 32768u;
        uint32_t KLs = KHs + 8192u, VHs = KHs + 16384u;

        float Sc[8][4];
        #pragma unroll
        for (int nf = 0; nf < 8; nf++)
            Sc[nf][0] = Sc[nf][1] = Sc[nf][2] = Sc[nf][3] = 0.f;
        #pragma unroll
        for (int ks = 0; ks < 4; ks++) {
            uint32_t ah[4], al[4];
            {
                int r = r0 + (lid & 15);
                int u = ks * 2 + (lid >> 4);
                ldsm_x4(ah, QH + sw128((uint32_t)(r * 128 + u * 16)));
                ldsm_x4(al, QL + sw128((uint32_t)(r * 128 + u * 16)));
            }
            #pragma unroll
            for (int ntp = 0; ntp < 4; ntp++) {
                int rb = ntp * 16 + ((lid >> 4) << 3) + (lid & 7);
                int u = ks * 2 + ((lid >> 3) & 1);
                uint32_t bh[4], bl[4];
                ldsm_x4(bh, KHs + sw128((uint32_t)(rb * 128 + u * 16)));
                ldsm_x4(bl, KLs + sw128((uint32_t)(rb * 128 + u * 16)));
                mma_f16(Sc[ntp * 2], ah, bh);
                mma_f16(Sc[ntp * 2], ah, bl);
                mma_f16(Sc[ntp * 2], al, bh);
                mma_f16(Sc[ntp * 2 + 1], ah, bh + 2);
                mma_f16(Sc[ntp * 2 + 1], ah, bl + 2);
                mma_f16(Sc[ntp * 2 + 1], al, bh + 2);
            }
        }

        float mx0 = -1e30f, mx1 = -1e30f;
        #pragma unroll
        for (int nf = 0; nf < 8; nf++) {
            mx0 = fmaxf(mx0, fmaxf(Sc[nf][0], Sc[nf][1]));
            mx1 = fmaxf(mx1, fmaxf(Sc[nf][2], Sc[nf][3]));
        }
        mx0 = fmaxf(mx0, __shfl_xor_sync(0xffffffffu, mx0, 1));
        mx0 = fmaxf(mx0, __shfl_xor_sync(0xffffffffu, mx0, 2));
        mx1 = fmaxf(mx1, __shfl_xor_sync(0xffffffffu, mx1, 1));
        mx1 = fmaxf(mx1, __shfl_xor_sync(0xffffffffu, mx1, 2));
        float mn0 = fmaxf(m0, mx0), mn1 = fmaxf(m1, mx1);
        float al0 = __expf(m0 - mn0), al1 = __expf(m1 - mn1);
        float s0 = 0.f, s1 = 0.f;
        #pragma unroll
        for (int nf = 0; nf < 8; nf++) {
            Sc[nf][0] = __expf(Sc[nf][0] - mn0);
            Sc[nf][1] = __expf(Sc[nf][1] - mn0);
            Sc[nf][2] = __expf(Sc[nf][2] - mn1);
            Sc[nf][3] = __expf(Sc[nf][3] - mn1);
            s0 += Sc[nf][0] + Sc[nf][1];
            s1 += Sc[nf][2] + Sc[nf][3];
        }
        s0 += __shfl_xor_sync(0xffffffffu, s0, 1);
        s0 += __shfl_xor_sync(0xffffffffu, s0, 2);
        s1 += __shfl_xor_sync(0xffffffffu, s1, 1);
        s1 += __shfl_xor_sync(0xffffffffu, s1, 2);
        l0 = l0 * al0 + s0;
        l1 = l1 * al1 + s1;
        m0 = mn0; m1 = mn1;
        #pragma unroll
        for (int nf = 0; nf < 8; nf++) {
            Oa[nf][0] *= al0; Oa[nf][1] *= al0;
            Oa[nf][2] *= al1; Oa[nf][3] *= al1;
        }

        #pragma unroll
        for (int t = 0; t < 4; t++) {
            uint32_t pah[4];
            pah[0] = pack_hi(Sc[2 * t][0], Sc[2 * t][1]);
            pah[1] = pack_hi(Sc[2 * t][2], Sc[2 * t][3]);
            pah[2] = pack_hi(Sc[2 * t + 1][0], Sc[2 * t + 1][1]);
            pah[3] = pack_hi(Sc[2 * t + 1][2], Sc[2 * t + 1][3]);
            #pragma unroll
            for (int ndp = 0; ndp < 4; ndp++) {
                int rb = t * 16 + ((lid >> 3) & 1) * 8 + (lid & 7);
                int u = ndp * 2 + (lid >> 4);
                uint32_t bh[4];
                ldsm_x4_t(bh, VHs + sw128((uint32_t)(rb * 128 + u * 16)));
                mma_f16(Oa[ndp * 2], pah, bh);
                mma_f16(Oa[ndp * 2 + 1], pah, bh + 2);
            }
        }
        __syncthreads();
    }

    float li0 = 1.f / l0, li1 = 1.f / l1;
    int r = r0 + grp;
    #pragma unroll
    for (int nf = 0; nf < 8; nf++) {
        int col = nf * 8 + qd * 2;
        float a0 = Oa[nf][0] * li0, a1 = Oa[nf][1] * li0;
        float b0 = Oa[nf][2] * li1, b1 = Oa[nf][3] * li1;
        *(uint32_t*)(oh + obase + (size_t)r * C_ + col) = pack_hi(a0, a1);
        *(uint32_t*)(ol + obase + (size_t)r * C_ + col) = pack_lo(a0, a1);
        *(uint32_t*)(oh + obase + (size_t)(r + 8) * C_ + col) = pack_hi(b0, b1);
        *(uint32_t*)(ol + obase + (size_t)(r + 8) * C_ + col) = pack_lo(b0, b1);
    }
}

// ---------------- launch ----------------
extern "C" void kernel_launch(void* const* d_in, const int* in_sizes, int n_in,
                              void* d_out, int out_size) {
    (void)in_sizes; (void)n_in; (void)out_size;
    const float* x    = (const float*)d_in[0];
    const float* K_W  = (const float*)d_in[2];
    const float* K_b  = (const float*)d_in[3];
    const float* Q_W  = (const float*)d_in[4];
    const float* Q_b  = (const float*)d_in[5];
    const float* V_W  = (const float*)d_in[6];
    const float* V_b  = (const float*)d_in[7];
    const float* O_W  = (const float*)d_in[8];
    const float* O_b  = (const float*)d_in[9];
    const float* ln1g = (const float*)d_in[10];
    const float* ln1b = (const float*)d_in[11];
    const float* ln2g = (const float*)d_in[12];
    const float* ln2b = (const float*)d_in[13];
    const float* W1   = (const float*)d_in[14];
    const float* b1   = (const float*)d_in[15];
    const float* W2   = (const float*)d_in[16];
    const float* b2   = (const float*)d_in[17];
    float* out = (float*)d_out;

    float *p_xs, *p_out1, *p_bqkv;
    __half *p_resh, *p_resl, *p_qkvh, *p_qkvl, *p_oh, *p_ol, *p_hh, *p_hl,
           *p_h1h, *p_h1l, *p_wqh, *p_wql, *p_woh, *p_wol,
           *p_w1h, *p_w1l, *p_w2h, *p_w2l;
    cudaGetSymbolAddress((void**)&p_xs, g_xs);
    cudaGetSymbolAddress((void**)&p_out1, g_out1);
    cudaGetSymbolAddress((void**)&p_bqkv, g_bqkv);
    cudaGetSymbolAddress((void**)&p_resh, g_res_h);
    cudaGetSymbolAddress((void**)&p_resl, g_res_l);
    cudaGetSymbolAddress((void**)&p_qkvh, g_qkv_h);
    cudaGetSymbolAddress((void**)&p_qkvl, g_qkv_l);
    cudaGetSymbolAddress((void**)&p_oh, g_o_h);
    cudaGetSymbolAddress((void**)&p_ol, g_o_l);
    cudaGetSymbolAddress((void**)&p_hh, g_h_h);
    cudaGetSymbolAddress((void**)&p_hl, g_h_l);
    cudaGetSymbolAddress((void**)&p_h1h, g_h1_h);
    cudaGetSymbolAddress((void**)&p_h1l, g_h1_l);
    cudaGetSymbolAddress((void**)&p_wqh, g_wqkv_h);
    cudaGetSymbolAddress((void**)&p_wql, g_wqkv_l);
    cudaGetSymbolAddress((void**)&p_woh, g_wo_h);
    cudaGetSymbolAddress((void**)&p_wol, g_wo_l);
    cudaGetSymbolAddress((void**)&p_w1h, g_w1_h);
    cudaGetSymbolAddress((void**)&p_w1l, g_w1_l);
    cudaGetSymbolAddress((void**)&p_w2h, g_w2_h);
    cudaGetSymbolAddress((void**)&p_w2l, g_w2_l);

    cudaFuncSetAttribute(ln1_fused, cudaFuncAttributeMaxDynamicSharedMemorySize, LN1_SMEM);
    cudaFuncSetAttribute(attn4, cudaFuncAttributeMaxDynamicSharedMemorySize, ATT_SMEM);
    cudaFuncSetAttribute(qkv_gemm, cudaFuncAttributeMaxDynamicSharedMemorySize, GEMM_SMEM);
    cudaFuncSetAttribute(tc_gemm5<0, 1, 0, 2>, cudaFuncAttributeMaxDynamicSharedMemorySize, GEMM_SMEM);
    cudaFuncSetAttribute(tc_gemm5<1, 0, 1, 1>, cudaFuncAttributeMaxDynamicSharedMemorySize, GEMM_SMEM);
    cudaFuncSetAttribute(tc_gemm5<0, 1, 2, 1>, cudaFuncAttributeMaxDynamicSharedMemorySize, GEMM_SMEM);

    // launch order keeps the fused QKV GEMM in profile slot #4
    pack_qkvw<<<dim3(16, 2, 24), 256>>>(Q_W, K_W, V_W, p_wqh, p_wql);
    pack_bias<<<6, 256>>>(Q_b, K_b, V_b, p_bqkv);
    ln1_fused<<<256, 256, LN1_SMEM>>>(x, ln1g, ln1b, p_xs, p_resh, p_resl);
    qkv_gemm<<<dim3(6, 64), 512, GEMM_SMEM>>>(
        p_resh, p_resl, p_wqh, p_wql, p_bqkv, p_qkvh, p_qkvl);
    pack_w3<<<dim3(16, 16, 3), 256>>>(O_W, W1, W2, p_woh, p_wol, p_w1h, p_w1l, p_w2h, p_w2l);
    attn4<<<dim3(8, 8, 8), 256, ATT_SMEM>>>(p_qkvh, p_qkvl, p_oh, p_ol);
    tc_gemm5<0, 1, 0, 2><<<dim3(2, 64), 512, GEMM_SMEM>>>(
        p_oh, p_ol, p_woh, p_wol, O_b, p_xs, p_out1, nullptr, nullptr, C_);
    ln_rows_hl<<<M_, 256>>>(p_out1, ln2g, ln2b, p_hh, p_hl);
    tc_gemm5<1, 0, 1, 1><<<dim3(2, 64), 512, GEMM_SMEM>>>(
        p_hh, p_hl, p_w1h, p_w1l, b1, nullptr, nullptr, p_h1h, p_h1l, C_);
    tc_gemm5<0, 1, 2, 1><<<dim3(2, 64), 512, GEMM_SMEM>>>(
        p_h1h, p_h1l, p_w2h, p_w2l, b2, p_out1, out, nullptr, nullptr, C_);
}

// round 16
// speedup vs baseline: 1.0742x; 1.0742x over previous
#include <cuda_runtime.h>
#include <cuda_fp16.h>
#include <cstdint>
#include <cstddef>

#define B_ 8
#define C_ 512
#define S_ 1024
#define NH 8
#define HD 64
#define M_ (B_ * S_)   // 8192
#define NQKV 1536

// ---------------- scratch (device globals, no allocation) ----------------
__device__ __align__(16) float g_xs[M_ * C_];
__device__ __align__(16) float g_out1[M_ * C_];
__device__ __align__(16) __half g_res_h[M_ * C_];
__device__ __align__(16) __half g_res_l[M_ * C_];
__device__ __align__(16) __half g_qkv_h[M_ * NQKV];
__device__ __align__(16) __half g_qkv_l[M_ * NQKV];
__device__ __align__(16) __half g_o_h[M_ * C_];
__device__ __align__(16) __half g_o_l[M_ * C_];
__device__ __align__(16) __half g_h_h[M_ * C_];
__device__ __align__(16) __half g_h_l[M_ * C_];
__device__ __align__(16) __half g_h1_h[M_ * C_];
__device__ __align__(16) __half g_h1_l[M_ * C_];
__device__ __align__(16) __half g_wqkv_h[NQKV * C_];
__device__ __align__(16) __half g_wqkv_l[NQKV * C_];
__device__ __align__(16) __half g_wo_h[C_ * C_];
__device__ __align__(16) __half g_wo_l[C_ * C_];
__device__ __align__(16) __half g_w1_h[C_ * C_];
__device__ __align__(16) __half g_w1_l[C_ * C_];
__device__ __align__(16) __half g_w2_h[C_ * C_];
__device__ __align__(16) __half g_w2_l[C_ * C_];
__device__ float g_bqkv[NQKV];

// ---------------- PTX helpers (sm_80-level, valid on plain sm_103) ----------------
__device__ __forceinline__ uint32_t smem_to_u32(const void* p) {
    uint32_t a;
    asm("{ .reg .u64 t; cvta.to.shared.u64 t, %1; cvt.u32.u64 %0, t; }" : "=r"(a) : "l"(p));
    return a;
}
__device__ __forceinline__ uint32_t sw128(uint32_t off) { return off ^ ((off >> 3) & 0x70); }

__device__ __forceinline__ void mma_f16(float* c, const uint32_t* a, const uint32_t* b) {
    asm volatile(
        "mma.sync.aligned.m16n8k16.row.col.f32.f16.f16.f32 "
        "{%0,%1,%2,%3}, {%4,%5,%6,%7}, {%8,%9}, {%0,%1,%2,%3};"
        : "+f"(c[0]), "+f"(c[1]), "+f"(c[2]), "+f"(c[3])
        : "r"(a[0]), "r"(a[1]), "r"(a[2]), "r"(a[3]), "r"(b[0]), "r"(b[1]));
}
__device__ __forceinline__ void ldsm_x4(uint32_t* r, uint32_t addr) {
    asm volatile("ldmatrix.sync.aligned.m8n8.x4.shared.b16 {%0,%1,%2,%3}, [%4];"
        : "=r"(r[0]), "=r"(r[1]), "=r"(r[2]), "=r"(r[3]) : "r"(addr));
}
__device__ __forceinline__ void ldsm_x4_t(uint32_t* r, uint32_t addr) {
    asm volatile("ldmatrix.sync.aligned.m8n8.x4.trans.shared.b16 {%0,%1,%2,%3}, [%4];"
        : "=r"(r[0]), "=r"(r[1]), "=r"(r[2]), "=r"(r[3]) : "r"(addr));
}
#define CP_ASYNC16(dst, src) \
    asm volatile("cp.async.cg.shared.global [%0], [%1], 16;" :: "r"(dst), "l"(src))
#define CP_COMMIT() asm volatile("cp.async.commit_group;" ::: "memory")
#define CP_WAIT1() asm volatile("cp.async.wait_group 1;" ::: "memory")
#define CP_WAIT0() asm volatile("cp.async.wait_group 0;" ::: "memory")

// ---------------- small helpers ----------------
__device__ __forceinline__ float blockReduceSum(float v, float* red) {
    #pragma unroll
    for (int o = 16; o; o >>= 1) v += __shfl_xor_sync(0xffffffffu, v, o);
    int wid = threadIdx.x >> 5;
    if ((threadIdx.x & 31) == 0) red[wid] = v;
    __syncthreads();
    float r = (threadIdx.x < 8) ? red[threadIdx.x] : 0.f;
    if (threadIdx.x < 32) {
        #pragma unroll
        for (int o = 4; o; o >>= 1) r += __shfl_xor_sync(0xffffffffu, r, o);
        if (threadIdx.x == 0) red[0] = r;
    }
    __syncthreads();
    float out = red[0];
    __syncthreads();
    return out;
}
__device__ __forceinline__ void split_f16(float v, __half& h, __half& l) {
    h = __float2half_rn(v);
    l = __float2half_rn(v - __half2float(h));
}
__device__ __forceinline__ uint32_t pack_hi(float a, float b) {
    __half ha = __float2half_rn(a), hb = __float2half_rn(b);
    return ((uint32_t)__half_as_ushort(hb) << 16) | __half_as_ushort(ha);
}
__device__ __forceinline__ uint32_t pack_lo(float a, float b) {
    __half ha = __float2half_rn(a), hb = __float2half_rn(b);
    __half la = __float2half_rn(a - __half2float(ha));
    __half lb = __float2half_rn(b - __half2float(hb));
    return ((uint32_t)__half_as_ushort(lb) << 16) | __half_as_ushort(la);
}

// ---------------- pack kernels ----------------
__global__ void pack_qkvw(const float* __restrict__ QW, const float* __restrict__ KW,
                          const float* __restrict__ VW,
                          __half* __restrict__ wh, __half* __restrict__ wl) {
    __shared__ float t[32][33];
    int sel = blockIdx.z >> 3, n = blockIdx.z & 7;
    const float* src = sel == 0 ? QW : (sel == 1 ? KW : VW);
    float sc = sel == 0 ? 0.04419417382415922f : 1.f;
    int c0 = blockIdx.x * 32, d0 = blockIdx.y * 32;
    int lx = threadIdx.x & 31, ly = threadIdx.x >> 5;
    #pragma unroll
    for (int i = 0; i < 4; i++)
        t[ly + i * 8][lx] = src[((size_t)n * C_ + c0 + ly + i * 8) * HD + d0 + lx] * sc;
    __syncthreads();
    #pragma unroll
    for (int i = 0; i < 4; i++) {
        int row = sel * 512 + n * 64 + d0 + ly + i * 8;
        float v = t[lx][ly + i * 8];
        __half h, l; split_f16(v, h, l);
        wh[(size_t)row * C_ + c0 + lx] = h;
        wl[(size_t)row * C_ + c0 + lx] = l;
    }
}
__global__ void pack_w3(const float* __restrict__ OW, const float* __restrict__ W1,
                        const float* __restrict__ W2,
                        __half* __restrict__ oh, __half* __restrict__ ol,
                        __half* __restrict__ h1, __half* __restrict__ l1,
                        __half* __restrict__ h2, __half* __restrict__ l2) {
    __shared__ float t[32][33];
    const float* src = blockIdx.z == 0 ? OW : (blockIdx.z == 1 ? W1 : W2);
    __half* dh = blockIdx.z == 0 ? oh : (blockIdx.z == 1 ? h1 : h2);
    __half* dl = blockIdx.z == 0 ? ol : (blockIdx.z == 1 ? l1 : l2);
    int n0 = blockIdx.x * 32, k0 = blockIdx.y * 32;
    int lx = threadIdx.x & 31, ly = threadIdx.x >> 5;
    #pragma unroll
    for (int i = 0; i < 4; i++)
        t[ly + i * 8][lx] = src[(size_t)(k0 + ly + i * 8) * C_ + n0 + lx];
    __syncthreads();
    #pragma unroll
    for (int i = 0; i < 4; i++) {
        int n = n0 + ly + i * 8;
        float v = t[lx][ly + i * 8];
        __half h, l; split_f16(v, h, l);
        dh[(size_t)n * C_ + k0 + lx] = h;
        dl[(size_t)n * C_ + k0 + lx] = l;
    }
}
__global__ void pack_bias(const float* __restrict__ Qb, const float* __restrict__ Kb,
                          const float* __restrict__ Vb, float* __restrict__ b) {
    int j = blockIdx.x * blockDim.x + threadIdx.x;
    if (j < 512) b[j] = Qb[j] * 0.04419417382415922f;
    else if (j < 1024) b[j] = Kb[j - 512];
    else if (j < 1536) b[j] = Vb[j - 1024];
}

// ---------------- fused transpose + LayerNorm1 ----------------
static constexpr int LN1_SMEM = 512 * 36 * 4 + 256;
__global__ void __launch_bounds__(256)
ln1_fused(const float* __restrict__ x, const float* __restrict__ g,
          const float* __restrict__ bt, float* __restrict__ xs,
          __half* __restrict__ resh, __half* __restrict__ resl) {
    extern __shared__ float T[];   // [512][36] + stats[64]
    float* sred = T + 512 * 36;
    int tid = threadIdx.x;
    int bi = blockIdx.x >> 5;
    int s0 = (blockIdx.x & 31) * 32;
    #pragma unroll
    for (int it = 0; it < 64; it++) {
        int flat = tid + it * 256;
        int c = flat >> 5, s = flat & 31;
        T[c * 36 + s] = x[((size_t)bi * C_ + c) * S_ + s0 + s];
    }
    __syncthreads();
    int rt = tid >> 3, j = tid & 7;
    float sum = 0.f;
    #pragma unroll
    for (int i = 0; i < 64; i++) sum += T[(j + 8 * i) * 36 + rt];
    sum += __shfl_xor_sync(0xffffffffu, sum, 1);
    sum += __shfl_xor_sync(0xffffffffu, sum, 2);
    sum += __shfl_xor_sync(0xffffffffu, sum, 4);
    float mu = sum * (1.f / 512.f);
    float var = 0.f;
    #pragma unroll
    for (int i = 0; i < 64; i++) {
        float d = T[(j + 8 * i) * 36 + rt] - mu;
        var += d * d;
    }
    var += __shfl_xor_sync(0xffffffffu, var, 1);
    var += __shfl_xor_sync(0xffffffffu, var, 2);
    var += __shfl_xor_sync(0xffffffffu, var, 4);
    float rstd = rsqrtf(var * (1.f / 512.f) + 1e-5f);
    if (j == 0) { sred[rt * 2] = mu; sred[rt * 2 + 1] = rstd; }
    __syncthreads();
    #pragma unroll
    for (int it = 0; it < 32; it++) {
        int flat = tid + it * 256;
        int r = flat >> 8;
        int c2 = (flat & 255) * 2;
        float mur = sred[r * 2], rs = sred[r * 2 + 1];
        float v0 = T[c2 * 36 + r], v1 = T[(c2 + 1) * 36 + r];
        float y0 = (v0 - mur) * rs * g[c2] + bt[c2];
        float y1 = (v1 - mur) * rs * g[c2 + 1] + bt[c2 + 1];
        size_t row = (size_t)bi * S_ + s0 + r;
        *(float2*)(xs + row * C_ + c2) = make_float2(v0, v1);
        *(uint32_t*)(resh + row * C_ + c2) = pack_hi(y0, y1);
        *(uint32_t*)(resl + row * C_ + c2) = pack_lo(y0, y1);
    }
}

// ---------------- LayerNorm over rows -> fp16 hi/lo ----------------
__global__ void ln_rows_hl(const float* __restrict__ in, const float* __restrict__ g,
                           const float* __restrict__ bt,
                           __half* __restrict__ oh, __half* __restrict__ ol) {
    int row = blockIdx.x;
    int tid = threadIdx.x;
    __shared__ float red[8];
    const float* xp = in + (size_t)row * C_;
    float2 v = *(const float2*)(xp + tid * 2);
    float sum = blockReduceSum(v.x + v.y, red);
    float mu = sum * (1.f / 512.f);
    float d1 = v.x - mu, d2 = v.y - mu;
    float var = blockReduceSum(d1 * d1 + d2 * d2, red) * (1.f / 512.f);
    float rstd = rsqrtf(var + 1e-5f);
    float y1 = d1 * rstd * g[2 * tid] + bt[2 * tid];
    float y2 = d2 * rstd * g[2 * tid + 1] + bt[2 * tid + 1];
    *(uint32_t*)(oh + (size_t)row * C_ + 2 * tid) = pack_hi(y1, y2);
    *(uint32_t*)(ol + (size_t)row * C_ + 2 * tid) = pack_lo(y1, y2);
}

// ---------------- GEMM body: 128x128 tile, 256 thr, 3-stage cp.async, 2 CTA/SM ----------------
// TERMS: 3 = Ah*Bh+Ah*Bl+Al*Bh, 2 = Ah*Bh+Ah*Bl, 1 = Ah*Bh,
//        4 = Ah*Bh+Al*Bh (A hi/lo, B hi only)
// OUT: 0 = fp32 row-major, 1 = fp16 hi/lo, 2 = fp32 transposed BCHW via smem restage
// Stage: A 16KB + B 16KB = 32KB; 3 stages = 96KB; 2 CTA/SM = 192KB <= 228KB
static constexpr int GEMM_SMEM = 98304;

template <int ACT, int RESID, int OUT, int TERMS>
__device__ __forceinline__ void gemm_body(
        char* smem,
        const __half* __restrict__ Ah, const __half* __restrict__ Al,
        const __half* __restrict__ Bh, const __half* __restrict__ Bl,
        const float* __restrict__ bias, const float* __restrict__ resid,
        float* __restrict__ outf, __half* __restrict__ outh,
        __half* __restrict__ outl, int ldo, int col0, int row0) {
    constexpr bool A_LO = (TERMS == 3 || TERMS == 4);
    constexpr bool B_LO = (TERMS == 3 || TERMS == 2);
    uint32_t sb = smem_to_u32(smem);
    int tid = threadIdx.x, wid = tid >> 5, lid = tid & 31;
    int grp = lid >> 2, qd = lid & 3;
    int m_base = (wid >> 1) * 32, n_base = (wid & 1) * 64;
    float acc[2][8][4] = {};

    auto issue = [&](int c) {
        int k0 = c * 32;
        uint32_t st = sb + (uint32_t)(c % 3) * 32768u;
        #pragma unroll
        for (int it = 0; it < (A_LO ? 4 : 2); it++) {
            int idx = tid + it * 256;
            int hl = idx >> 9, rem = idx & 511, r = rem >> 2, u = rem & 3;
            const __half* src = (hl ? Al : Ah) + (size_t)(row0 + r) * C_ + k0 + u * 8;
            CP_ASYNC16(st + sw128((uint32_t)(r * 128 + hl * 64 + u * 16)), src);
        }
        #pragma unroll
        for (int it = 0; it < (B_LO ? 4 : 2); it++) {
            int idx = tid + it * 256;
            int hl = idx >> 9, rem = idx & 511, r = rem >> 2, u = rem & 3;
            const __half* src = (hl ? Bl : Bh) + (size_t)(col0 + r) * C_ + k0 + u * 8;
            CP_ASYNC16(st + 16384u + sw128((uint32_t)(r * 128 + hl * 64 + u * 16)), src);
        }
    };
    issue(0); CP_COMMIT();
    issue(1); CP_COMMIT();

    for (int c = 0; c < 16; c++) {
        if (c < 15) CP_WAIT1(); else CP_WAIT0();
        __syncthreads();   // orders compute(c-1) before issue(c+2) overwrite of buf (c-1)%3
        if (c + 2 < 16) { issue(c + 2); CP_COMMIT(); }
        uint32_t Ab = sb + (uint32_t)(c % 3) * 32768u, Bb = Ab + 16384u;
        #pragma unroll
        for (int ks = 0; ks < 2; ks++) {
            uint32_t ah[2][4], al[2][4];
            #pragma unroll
            for (int f2 = 0; f2 < 2; f2++) {
                int r = m_base + f2 * 16 + (lid & 15);
                int u = ks * 2 + (lid >> 4);
                ldsm_x4(ah[f2], Ab + sw128((uint32_t)(r * 128 + u * 16)));
                if (A_LO)
                    ldsm_x4(al[f2], Ab + sw128((uint32_t)(r * 128 + 64 + u * 16)));
            }
            #pragma unroll
            for (int ntp = 0; ntp < 4; ntp++) {
                int rb = n_base + ntp * 16 + ((lid >> 4) << 3) + (lid & 7);
                int u = ks * 2 + ((lid >> 3) & 1);
                uint32_t bh[4], bl[4];
                ldsm_x4(bh, Bb + sw128((uint32_t)(rb * 128 + u * 16)));
                if (B_LO)
                    ldsm_x4(bl, Bb + sw128((uint32_t)(rb * 128 + 64 + u * 16)));
                #pragma unroll
                for (int f2 = 0; f2 < 2; f2++) {
                    mma_f16(acc[f2][ntp * 2], ah[f2], bh);
                    if (B_LO) mma_f16(acc[f2][ntp * 2], ah[f2], bl);
                    if (A_LO && TERMS != 2) mma_f16(acc[f2][ntp * 2], al[f2], bh);
                    mma_f16(acc[f2][ntp * 2 + 1], ah[f2], bh + 2);
                    if (B_LO) mma_f16(acc[f2][ntp * 2 + 1], ah[f2], bl + 2);
                    if (A_LO && TERMS != 2) mma_f16(acc[f2][ntp * 2 + 1], al[f2], bh + 2);
                }
            }
        }
    }
    __syncthreads();

    if (OUT == 2) {
        // transpose epilogue: stage 64-col halves as fp32 [64][132] then write BCHW
        float* T = (float*)smem;
        int b = row0 >> 10, s0 = row0 & 1023;
        #pragma unroll
        for (int half = 0; half < 2; half++) {
            __syncthreads();
            if ((wid & 1) == half) {
                #pragma unroll
                for (int f2 = 0; f2 < 2; f2++) {
                    #pragma unroll
                    for (int rr = 0; rr < 2; rr++) {
                        int rloc = m_base + f2 * 16 + grp + rr * 8;
                        #pragma unroll
                        for (int t = 0; t < 8; t++) {
                            int lc = t * 8 + qd * 2;
                            int col = col0 + half * 64 + lc;
                            float v0 = acc[f2][t][rr * 2 + 0] + bias[col];
                            float v1 = acc[f2][t][rr * 2 + 1] + bias[col + 1];
                            if (RESID) {
                                float2 rv = *(const float2*)(resid + (size_t)(row0 + rloc) * C_ + col);
                                v0 += rv.x; v1 += rv.y;
                            }
                            T[lc * 132 + rloc] = v0;
                            T[(lc + 1) * 132 + rloc] = v1;
                        }
                    }
                }
            }
            __syncthreads();
            #pragma unroll
            for (int it = 0; it < 32; it++) {
                int flat = tid + it * 256;
                int lc = flat >> 7, rr = flat & 127;
                outf[((size_t)b * C_ + col0 + half * 64 + lc) * S_ + s0 + rr] = T[lc * 132 + rr];
            }
        }
    } else {
        #pragma unroll
        for (int f2 = 0; f2 < 2; f2++) {
            #pragma unroll
            for (int rr = 0; rr < 2; rr++) {
                int r = row0 + m_base + f2 * 16 + grp + rr * 8;
                #pragma unroll
                for (int t = 0; t < 8; t++) {
                    int col = col0 + n_base + t * 8 + qd * 2;
                    float v0 = acc[f2][t][rr * 2 + 0] + bias[col];
                    float v1 = acc[f2][t][rr * 2 + 1] + bias[col + 1];
                    if (ACT == 1) {
                        v0 = 0.5f * v0 * (1.f + erff(v0 * 0.7071067811865476f));
                        v1 = 0.5f * v1 * (1.f + erff(v1 * 0.7071067811865476f));
                    }
                    if (RESID) {
                        float2 rv = *(const float2*)(resid + (size_t)r * C_ + col);
                        v0 += rv.x; v1 += rv.y;
                    }
                    if (OUT == 1) {
                        *(uint32_t*)(outh + (size_t)r * ldo + col) = pack_hi(v0, v1);
                        *(uint32_t*)(outl + (size_t)r * ldo + col) = pack_lo(v0, v1);
                    } else {
                        *(float2*)(outf + (size_t)r * ldo + col) = make_float2(v0, v1);
                    }
                }
            }
        }
    }
}

template <int ACT, int RESID, int OUT, int TERMS>
__global__ void __launch_bounds__(256, 2)
tc_gemm3(const __half* __restrict__ Ah, const __half* __restrict__ Al,
         const __half* __restrict__ Bh, const __half* __restrict__ Bl,
         const float* __restrict__ bias, const float* __restrict__ resid,
         float* __restrict__ outf, __half* __restrict__ outh,
         __half* __restrict__ outl, int ldo) {
    extern __shared__ char smem[];
    gemm_body<ACT, RESID, OUT, TERMS>(smem, Ah, Al, Bh, Bl, bias, resid,
                                      outf, outh, outl, ldo,
                                      blockIdx.x * 128, blockIdx.y * 128);
}

// fused QKV projection: cols 0..1023 (q,k) 3-term, cols 1024..1535 (v) TERMS=4
__global__ void __launch_bounds__(256, 2)
qkv_gemm(const __half* __restrict__ Ah, const __half* __restrict__ Al,
         const __half* __restrict__ Bh, const __half* __restrict__ Bl,
         const float* __restrict__ bias,
         __half* __restrict__ outh, __half* __restrict__ outl) {
    extern __shared__ char smem[];
    int col0 = blockIdx.x * 128, row0 = blockIdx.y * 128;
    if (blockIdx.x < 8)
        gemm_body<0, 0, 1, 3>(smem, Ah, Al, Bh, Bl, bias, nullptr,
                              nullptr, outh, outl, NQKV, col0, row0);
    else
        gemm_body<0, 0, 1, 4>(smem, Ah, Al, Bh, Bl, bias, nullptr,
                              nullptr, outh, outl, NQKV, col0, row0);
}

// ---------------- flash attention: QK 3-term, PV 1-term (V hi only) ----------------
// SMEM: QH 16K | QL 16K | 2 KV stages x 32K (KH|KL|VH used, 8K hole) = 96KB
static constexpr int ATT_SMEM = 98304;

__global__ void __launch_bounds__(256, 2)
attn4(const __half* __restrict__ qh, const __half* __restrict__ ql,
      __half* __restrict__ oh, __half* __restrict__ ol) {
    extern __shared__ char smem[];
    uint32_t sb = smem_to_u32(smem);
    const uint32_t QH = sb, QL = sb + 16384u;
    int tid = threadIdx.x, wid = tid >> 5, lid = tid & 31;
    int grp = lid >> 2, qd = lid & 3;
    int qt = blockIdx.x, n = blockIdx.y, b = blockIdx.z;
    size_t qrow0 = (size_t)(b * S_ + qt * 128);
    size_t obase = qrow0 * C_ + n * HD;
    int r0 = wid * 16;

    auto issue_kv = [&](int kt) {
        uint32_t st = sb + 32768u + (uint32_t)(kt & 1) * 32768u;
        #pragma unroll
        for (int it = 0; it < 6; it++) {
            int idx = tid + it * 256;
            int buf = idx >> 9, rem = idx & 511, r = rem >> 3, u = rem & 7;
            const __half* base = (buf == 1) ? ql : qh;
            int off = (buf == 2) ? 1024 : 512;
            const __half* src = base +
                (size_t)(b * S_ + kt * 64 + r) * NQKV + off + n * HD + u * 8;
            CP_ASYNC16(st + (uint32_t)(buf * 8192) +
                       sw128((uint32_t)(r * 128 + u * 16)), src);
        }
    };
    #pragma unroll
    for (int it = 0; it < 8; it++) {
        int idx = tid + it * 256;
        int hl = idx >> 10, rem = idx & 1023, r = rem >> 3, u = rem & 7;
        const __half* src = (hl ? ql : qh) + (qrow0 + r) * NQKV + n * HD + u * 8;
        CP_ASYNC16((hl ? QL : QH) + sw128((uint32_t)(r * 128 + u * 16)), src);
    }
    issue_kv(0); CP_COMMIT();

    float Oa[8][4] = {};
    float m0 = -1e30f, m1 = -1e30f, l0 = 0.f, l1 = 0.f;

    for (int kt = 0; kt < 16; kt++) {
        CP_WAIT0();
        __syncthreads();
        if (kt + 1 < 16) { issue_kv(kt + 1); CP_COMMIT(); }
        uint32_t KHs = sb + 32768u + (uint32_t)(kt & 1) * 32768u;
        uint32_t KLs = KHs + 8192u, VHs = KHs + 16384u;

        float Sc[8][4];
        #pragma unroll
        for (int nf = 0; nf < 8; nf++)
            Sc[nf][0] = Sc[nf][1] = Sc[nf][2] = Sc[nf][3] = 0.f;
        #pragma unroll
        for (int ks = 0; ks < 4; ks++) {
            uint32_t ah[4], al[4];
            {
                int r = r0 + (lid & 15);
                int u = ks * 2 + (lid >> 4);
                ldsm_x4(ah, QH + sw128((uint32_t)(r * 128 + u * 16)));
                ldsm_x4(al, QL + sw128((uint32_t)(r * 128 + u * 16)));
            }
            #pragma unroll
            for (int ntp = 0; ntp < 4; ntp++) {
                int rb = ntp * 16 + ((lid >> 4) << 3) + (lid & 7);
                int u = ks * 2 + ((lid >> 3) & 1);
                uint32_t bh[4], bl[4];
                ldsm_x4(bh, KHs + sw128((uint32_t)(rb * 128 + u * 16)));
                ldsm_x4(bl, KLs + sw128((uint32_t)(rb * 128 + u * 16)));
                mma_f16(Sc[ntp * 2], ah, bh);
                mma_f16(Sc[ntp * 2], ah, bl);
                mma_f16(Sc[ntp * 2], al, bh);
                mma_f16(Sc[ntp * 2 + 1], ah, bh + 2);
                mma_f16(Sc[ntp * 2 + 1], ah, bl + 2);
                mma_f16(Sc[ntp * 2 + 1], al, bh + 2);
            }
        }

        float mx0 = -1e30f, mx1 = -1e30f;
        #pragma unroll
        for (int nf = 0; nf < 8; nf++) {
            mx0 = fmaxf(mx0, fmaxf(Sc[nf][0], Sc[nf][1]));
            mx1 = fmaxf(mx1, fmaxf(Sc[nf][2], Sc[nf][3]));
        }
        mx0 = fmaxf(mx0, __shfl_xor_sync(0xffffffffu, mx0, 1));
        mx0 = fmaxf(mx0, __shfl_xor_sync(0xffffffffu, mx0, 2));
        mx1 = fmaxf(mx1, __shfl_xor_sync(0xffffffffu, mx1, 1));
        mx1 = fmaxf(mx1, __shfl_xor_sync(0xffffffffu, mx1, 2));
        float mn0 = fmaxf(m0, mx0), mn1 = fmaxf(m1, mx1);
        float al0 = __expf(m0 - mn0), al1 = __expf(m1 - mn1);
        float s0 = 0.f, s1 = 0.f;
        #pragma unroll
        for (int nf = 0; nf < 8; nf++) {
            Sc[nf][0] = __expf(Sc[nf][0] - mn0);
            Sc[nf][1] = __expf(Sc[nf][1] - mn0);
            Sc[nf][2] = __expf(Sc[nf][2] - mn1);
            Sc[nf][3] = __expf(Sc[nf][3] - mn1);
            s0 += Sc[nf][0] + Sc[nf][1];
            s1 += Sc[nf][2] + Sc[nf][3];
        }
        s0 += __shfl_xor_sync(0xffffffffu, s0, 1);
        s0 += __shfl_xor_sync(0xffffffffu, s0, 2);
        s1 += __shfl_xor_sync(0xffffffffu, s1, 1);
        s1 += __shfl_xor_sync(0xffffffffu, s1, 2);
        l0 = l0 * al0 + s0;
        l1 = l1 * al1 + s1;
        m0 = mn0; m1 = mn1;
        #pragma unroll
        for (int nf = 0; nf < 8; nf++) {
            Oa[nf][0] *= al0; Oa[nf][1] *= al0;
            Oa[nf][2] *= al1; Oa[nf][3] *= al1;
        }

        #pragma unroll
        for (int t = 0; t < 4; t++) {
            uint32_t pah[4];
            pah[0] = pack_hi(Sc[2 * t][0], Sc[2 * t][1]);
            pah[1] = pack_hi(Sc[2 * t][2], Sc[2 * t][3]);
            pah[2] = pack_hi(Sc[2 * t + 1][0], Sc[2 * t + 1][1]);
            pah[3] = pack_hi(Sc[2 * t + 1][2], Sc[2 * t + 1][3]);
            #pragma unroll
            for (int ndp = 0; ndp < 4; ndp++) {
                int rb = t * 16 + ((lid >> 3) & 1) * 8 + (lid & 7);
                int u = ndp * 2 + (lid >> 4);
                uint32_t bh[4];
                ldsm_x4_t(bh, VHs + sw128((uint32_t)(rb * 128 + u * 16)));
                mma_f16(Oa[ndp * 2], pah, bh);
                mma_f16(Oa[ndp * 2 + 1], pah, bh + 2);
            }
        }
        __syncthreads();
    }

    float li0 = 1.f / l0, li1 = 1.f / l1;
    int r = r0 + grp;
    #pragma unroll
    for (int nf = 0; nf < 8; nf++) {
        int col = nf * 8 + qd * 2;
        float a0 = Oa[nf][0] * li0, a1 = Oa[nf][1] * li0;
        float b0 = Oa[nf][2] * li1, b1 = Oa[nf][3] * li1;
        *(uint32_t*)(oh + obase + (size_t)r * C_ + col) = pack_hi(a0, a1);
        *(uint32_t*)(ol + obase + (size_t)r * C_ + col) = pack_lo(a0, a1);
        *(uint32_t*)(oh + obase + (size_t)(r + 8) * C_ + col) = pack_hi(b0, b1);
        *(uint32_t*)(ol + obase + (size_t)(r + 8) * C_ + col) = pack_lo(b0, b1);
    }
}

// ---------------- launch ----------------
extern "C" void kernel_launch(void* const* d_in, const int* in_sizes, int n_in,
                              void* d_out, int out_size) {
    (void)in_sizes; (void)n_in; (void)out_size;
    const float* x    = (const float*)d_in[0];
    const float* K_W  = (const float*)d_in[2];
    const float* K_b  = (const float*)d_in[3];
    const float* Q_W  = (const float*)d_in[4];
    const float* Q_b  = (const float*)d_in[5];
    const float* V_W  = (const float*)d_in[6];
    const float* V_b  = (const float*)d_in[7];
    const float* O_W  = (const float*)d_in[8];
    const float* O_b  = (const float*)d_in[9];
    const float* ln1g = (const float*)d_in[10];
    const float* ln1b = (const float*)d_in[11];
    const float* ln2g = (const float*)d_in[12];
    const float* ln2b = (const float*)d_in[13];
    const float* W1   = (const float*)d_in[14];
    const float* b1   = (const float*)d_in[15];
    const float* W2   = (const float*)d_in[16];
    const float* b2   = (const float*)d_in[17];
    float* out = (float*)d_out;

    float *p_xs, *p_out1, *p_bqkv;
    __half *p_resh, *p_resl, *p_qkvh, *p_qkvl, *p_oh, *p_ol, *p_hh, *p_hl,
           *p_h1h, *p_h1l, *p_wqh, *p_wql, *p_woh, *p_wol,
           *p_w1h, *p_w1l, *p_w2h, *p_w2l;
    cudaGetSymbolAddress((void**)&p_xs, g_xs);
    cudaGetSymbolAddress((void**)&p_out1, g_out1);
    cudaGetSymbolAddress((void**)&p_bqkv, g_bqkv);
    cudaGetSymbolAddress((void**)&p_resh, g_res_h);
    cudaGetSymbolAddress((void**)&p_resl, g_res_l);
    cudaGetSymbolAddress((void**)&p_qkvh, g_qkv_h);
    cudaGetSymbolAddress((void**)&p_qkvl, g_qkv_l);
    cudaGetSymbolAddress((void**)&p_oh, g_o_h);
    cudaGetSymbolAddress((void**)&p_ol, g_o_l);
    cudaGetSymbolAddress((void**)&p_hh, g_h_h);
    cudaGetSymbolAddress((void**)&p_hl, g_h_l);
    cudaGetSymbolAddress((void**)&p_h1h, g_h1_h);
    cudaGetSymbolAddress((void**)&p_h1l, g_h1_l);
    cudaGetSymbolAddress((void**)&p_wqh, g_wqkv_h);
    cudaGetSymbolAddress((void**)&p_wql, g_wqkv_l);
    cudaGetSymbolAddress((void**)&p_woh, g_wo_h);
    cudaGetSymbolAddress((void**)&p_wol, g_wo_l);
    cudaGetSymbolAddress((void**)&p_w1h, g_w1_h);
    cudaGetSymbolAddress((void**)&p_w1l, g_w1_l);
    cudaGetSymbolAddress((void**)&p_w2h, g_w2_h);
    cudaGetSymbolAddress((void**)&p_w2l, g_w2_l);

    cudaFuncSetAttribute(ln1_fused, cudaFuncAttributeMaxDynamicSharedMemorySize, LN1_SMEM);
    cudaFuncSetAttribute(attn4, cudaFuncAttributeMaxDynamicSharedMemorySize, ATT_SMEM);
    cudaFuncSetAttribute(qkv_gemm, cudaFuncAttributeMaxDynamicSharedMemorySize, GEMM_SMEM);
    cudaFuncSetAttribute(tc_gemm3<0, 1, 0, 2>, cudaFuncAttributeMaxDynamicSharedMemorySize, GEMM_SMEM);
    cudaFuncSetAttribute(tc_gemm3<1, 0, 1, 1>, cudaFuncAttributeMaxDynamicSharedMemorySize, GEMM_SMEM);
    cudaFuncSetAttribute(tc_gemm3<0, 1, 2, 1>, cudaFuncAttributeMaxDynamicSharedMemorySize, GEMM_SMEM);

    // launch order keeps the fused QKV GEMM in profile slot #4
    pack_qkvw<<<dim3(16, 2, 24), 256>>>(Q_W, K_W, V_W, p_wqh, p_wql);
    pack_bias<<<6, 256>>>(Q_b, K_b, V_b, p_bqkv);
    ln1_fused<<<256, 256, LN1_SMEM>>>(x, ln1g, ln1b, p_xs, p_resh, p_resl);
    qkv_gemm<<<dim3(12, 64), 256, GEMM_SMEM>>>(
        p_resh, p_resl, p_wqh, p_wql, p_bqkv, p_qkvh, p_qkvl);
    pack_w3<<<dim3(16, 16, 3), 256>>>(O_W, W1, W2, p_woh, p_wol, p_w1h, p_w1l, p_w2h, p_w2l);
    attn4<<<dim3(8, 8, 8), 256, ATT_SMEM>>>(p_qkvh, p_qkvl, p_oh, p_ol);
    tc_gemm3<0, 1, 0, 2><<<dim3(4, 64), 256, GEMM_SMEM>>>(
        p_oh, p_ol, p_woh, p_wol, O_b, p_xs, p_out1, nullptr, nullptr, C_);
    ln_rows_hl<<<M_, 256>>>(p_out1, ln2g, ln2b, p_hh, p_hl);
    tc_gemm3<1, 0, 1, 1><<<dim3(4, 64), 256, GEMM_SMEM>>>(
        p_hh, p_hl, p_w1h, p_w1l, b1, nullptr, nullptr, p_h1h, p_h1l, C_);
    tc_gemm3<0, 1, 2, 1><<<dim3(4, 64), 256, GEMM_SMEM>>>(
        p_h1h, p_h1l, p_w2h, p_w2l, b2, p_out1, out, nullptr, nullptr, C_);
}